// round 14
// baseline (speedup 1.0000x reference)
#include <cuda_runtime.h>
#include <cuda_fp16.h>
#include <cstdint>

// Problem constants (fixed by dataset)
#define MAXN   50000
#define NFEAT  512
#define FHID   256
#define FOUT   64

// Scratch (device globals: allocation-free per harness rules)
__device__ __align__(16) __half g_h1 [MAXN * FHID];    // x @ W1          (fp16)
__device__ __align__(16) __half g_h2 [MAXN * FHID];    // spmm(h1) + b1   (fp16)
__device__ __align__(16) __half g_h3 [MAXN * FOUT];    // relu(h2) @ W2   (fp16)
__device__ __align__(16) __half g_w1t[FHID * NFEAT];   // W1^T fp16
__device__ __align__(16) __half g_w2t[FOUT * FHID];    // W2^T fp16
__device__ int g_rowptr[MAXN + 1];

// ===========================================================================
// helpers
// ===========================================================================
__device__ __forceinline__ uint32_t smem_u32(const void* p) {
    uint32_t a;
    asm("{ .reg .u64 t; cvta.to.shared.u64 t, %1; cvt.u32.u64 %0, t; }"
        : "=r"(a) : "l"(p));
    return a;
}
__device__ __forceinline__ void cp16(uint32_t dst, const void* src) {
    asm volatile("cp.async.cg.shared.global [%0], [%1], 16;"
                 :: "r"(dst), "l"(src) : "memory");
}
// zero-fill variant: copies sz bytes (0 or 16), zeroes the rest
__device__ __forceinline__ void cp16z(uint32_t dst, const void* src, int sz) {
    asm volatile("cp.async.cg.shared.global [%0], [%1], 16, %2;"
                 :: "r"(dst), "l"(src), "r"(sz) : "memory");
}
#define CP_COMMIT() asm volatile("cp.async.commit_group;" ::: "memory")
#define CP_WAIT0()  asm volatile("cp.async.wait_group 0;" ::: "memory")
#define CP_WAIT2()  asm volatile("cp.async.wait_group 2;" ::: "memory")

// mma.sync m16n8k16 fp16 inputs, fp32 accum (base PTX, sm_80+)
__device__ __forceinline__ void mma16(float* d, const uint32_t* a, const uint32_t* b) {
    asm volatile(
        "mma.sync.aligned.m16n8k16.row.col.f32.f16.f16.f32 "
        "{%0,%1,%2,%3}, {%4,%5,%6,%7}, {%8,%9}, {%0,%1,%2,%3};"
        : "+f"(d[0]), "+f"(d[1]), "+f"(d[2]), "+f"(d[3])
        : "r"(a[0]), "r"(a[1]), "r"(a[2]), "r"(a[3]), "r"(b[0]), "r"(b[1]));
}

__device__ __forceinline__ uint32_t f2h2(float x, float y) {
    __half2 h = __floats2half2_rn(x, y);
    return *reinterpret_cast<uint32_t*>(&h);
}

// accumulate 8 halves (uint4) * w into fp32 acc[8]
__device__ __forceinline__ void acc8(float* a, uint4 v, float w) {
    const uint32_t* u = reinterpret_cast<const uint32_t*>(&v);
    #pragma unroll
    for (int q = 0; q < 4; q++) {
        float2 f = __half22float2(*reinterpret_cast<const __half2*>(&u[q]));
        a[2*q]   = fmaf(w, f.x, a[2*q]);
        a[2*q+1] = fmaf(w, f.y, a[2*q+1]);
    }
}

// ===========================================================================
// GEMM1 (R12-proven): 4 warps, warp tile 64x64, BM=128, BN=128, BK=32.
// A fp32 (cvt fp16 in registers), Bt fp16, C fp16.  LDSH=40 conflict-free.
// ===========================================================================
__global__ void __launch_bounds__(128)
gemm1_mma(const float* __restrict__ A, const __half* __restrict__ Bt,
          __half* __restrict__ C, int M, int K, int Ntot)
{
    constexpr int BM = 128, BN = 128, BK = 32, LDSH = 40;
    __shared__ __half As[2][BM * LDSH];
    __shared__ __half Bs[2][BN * LDSH];

    const int tid  = threadIdx.x;
    const int lane = tid & 31, wid = tid >> 5;
    const int g    = lane >> 2, tig = lane & 3;
    const int wm0  = (wid >> 1) * 64;
    const int wn0  = (wid & 1) * 64;
    const int blockM = blockIdx.y * BM;
    const int blockN = blockIdx.x * BN;

    const int arow = tid >> 3;                   // 0..15 (A rows: arow + 16i)
    const int aq   = tid & 7;

    float acc[4][8][4];
    #pragma unroll
    for (int mt = 0; mt < 4; mt++)
        #pragma unroll
        for (int nt = 0; nt < 8; nt++)
            #pragma unroll
            for (int i = 0; i < 4; i++) acc[mt][nt][i] = 0.f;

    auto ldgA = [&](int c, float4* av) {
        const int k0 = c * BK;
        #pragma unroll
        for (int i = 0; i < 8; i++) {
            int r = blockM + arow + i * 16;
            if (r < M)
                av[i] = *reinterpret_cast<const float4*>(&A[(size_t)r * K + k0 + aq * 4]);
            else
                av[i] = make_float4(0.f, 0.f, 0.f, 0.f);
        }
    };
    auto stsA = [&](int buf, float4* av) {
        #pragma unroll
        for (int i = 0; i < 8; i++) {
            float4 v = av[i];
            uint2 h = make_uint2(f2h2(v.x, v.y), f2h2(v.z, v.w));
            *reinterpret_cast<uint2*>(&As[buf][(arow + i * 16) * LDSH + aq * 4]) = h;
        }
    };
    auto cpB = [&](int c, int buf) {
        const int k0 = c * BK;
        #pragma unroll
        for (int i = 0; i < 4; i++) {
            int u = tid + i * 128;
            int r = u >> 2, q = u & 3;
            cp16(smem_u32(&Bs[buf][r * LDSH + q * 8]),
                 &Bt[(size_t)(blockN + r) * K + k0 + q * 8]);
        }
        CP_COMMIT();
    };
    auto compute = [&](int buf) {
        #pragma unroll
        for (int ks = 0; ks < 2; ks++) {
            uint32_t a[4][4], b[8][2];
            #pragma unroll
            for (int mt = 0; mt < 4; mt++) {
                const __half* p = &As[buf][(wm0 + mt * 16 + g) * LDSH + ks * 16 + 2 * tig];
                a[mt][0] = *reinterpret_cast<const uint32_t*>(p);
                a[mt][1] = *reinterpret_cast<const uint32_t*>(p + 8 * LDSH);
                a[mt][2] = *reinterpret_cast<const uint32_t*>(p + 8);
                a[mt][3] = *reinterpret_cast<const uint32_t*>(p + 8 * LDSH + 8);
            }
            #pragma unroll
            for (int nt = 0; nt < 8; nt++) {
                const __half* pb = &Bs[buf][(wn0 + nt * 8 + g) * LDSH + ks * 16 + 2 * tig];
                b[nt][0] = *reinterpret_cast<const uint32_t*>(pb);
                b[nt][1] = *reinterpret_cast<const uint32_t*>(pb + 8);
            }
            #pragma unroll
            for (int mt = 0; mt < 4; mt++)
                #pragma unroll
                for (int nt = 0; nt < 8; nt++)
                    mma16(acc[mt][nt], a[mt], b[nt]);
        }
    };

    {
        float4 av[8];
        ldgA(0, av);
        cpB(0, 0);
        stsA(0, av);
        CP_WAIT0();
        __syncthreads();
    }

    const int NC = K / BK;                       // 16
    for (int c = 0; c < NC; c++) {
        float4 av[8];
        const bool more = (c + 1 < NC);
        if (more) {
            ldgA(c + 1, av);
            cpB(c + 1, (c + 1) & 1);
        }
        compute(c & 1);
        if (more) {
            stsA((c + 1) & 1, av);
            CP_WAIT0();
            __syncthreads();
        }
    }

    #pragma unroll
    for (int mt = 0; mt < 4; mt++) {
        int r0 = blockM + wm0 + mt * 16 + g;
        int r1 = r0 + 8;
        #pragma unroll
        for (int nt = 0; nt < 8; nt++) {
            int cb = blockN + wn0 + nt * 8 + 2 * tig;
            if (r0 < M)
                *reinterpret_cast<uint32_t*>(&C[(size_t)r0 * Ntot + cb]) =
                    f2h2(acc[mt][nt][0], acc[mt][nt][1]);
            if (r1 < M)
                *reinterpret_cast<uint32_t*>(&C[(size_t)r1 * Ntot + cb]) =
                    f2h2(acc[mt][nt][2], acc[mt][nt][3]);
        }
    }
}

// ===========================================================================
// GEMM2: 4-stage cp.async pipeline for A AND B.  BM=128, BN=64, BK=16,
// 8 warps (2Mx4N, warp tile 64x16).  relu applied on A fragments (hmax2)
// after SMEM load — identical math to relu-before-staging.
// ===========================================================================
__global__ void __launch_bounds__(256)
gemm2_mma(const __half* __restrict__ A, const __half* __restrict__ Bt,
          __half* __restrict__ C, int M, int K, int Ntot)
{
    constexpr int BM = 128, BN = 64, BK = 16, LDSH = 24, WNT = 2, S = 4;
    __shared__ __half As[S][BM * LDSH];
    __shared__ __half Bs[S][BN * LDSH];

    const int tid  = threadIdx.x;
    const int lane = tid & 31, wid = tid >> 5;
    const int g    = lane >> 2, tig = lane & 3;
    const int wm0  = (wid >> 2) * 64;
    const int wn0  = (wid & 3) * (BN / 4);
    const int blockM = blockIdx.x * BM;

    float acc[4][WNT][4];
    #pragma unroll
    for (int mt = 0; mt < 4; mt++)
        #pragma unroll
        for (int nt = 0; nt < WNT; nt++)
            #pragma unroll
            for (int i = 0; i < 4; i++) acc[mt][nt][i] = 0.f;

    const __half2 hzero = __floats2half2_rn(0.f, 0.f);

    // one load = A tile (256 chunks) + B tile (128 chunks), single commit
    auto load = [&](int c) {
        const int k0 = c * BK;
        int buf = c % S;
        {   // A: r = tid>>1 (0..127), q = tid&1
            int r = tid >> 1, q = tid & 1;
            int gr = blockM + r;
            int sz = (gr < M) ? 16 : 0;
            if (gr >= M) gr = M - 1;
            cp16z(smem_u32(&As[buf][r * LDSH + q * 8]),
                  &A[(size_t)gr * K + k0 + q * 8], sz);
        }
        if (tid < BN * 2) {
            int r = tid >> 1, q = tid & 1;
            cp16(smem_u32(&Bs[buf][r * LDSH + q * 8]),
                 &Bt[(size_t)r * K + k0 + q * 8]);
        }
        CP_COMMIT();
    };

    auto compute = [&](int buf) {
        uint32_t a[4][4], b[WNT][2];
        #pragma unroll
        for (int mt = 0; mt < 4; mt++) {
            const __half* p = &As[buf][(wm0 + mt * 16 + g) * LDSH + 2 * tig];
            a[mt][0] = *reinterpret_cast<const uint32_t*>(p);
            a[mt][1] = *reinterpret_cast<const uint32_t*>(p + 8 * LDSH);
            a[mt][2] = *reinterpret_cast<const uint32_t*>(p + 8);
            a[mt][3] = *reinterpret_cast<const uint32_t*>(p + 8 * LDSH + 8);
            #pragma unroll
            for (int i = 0; i < 4; i++) {              // relu on fragments
                __half2* h = reinterpret_cast<__half2*>(&a[mt][i]);
                *h = __hmax2(*h, hzero);
            }
        }
        #pragma unroll
        for (int nt = 0; nt < WNT; nt++) {
            const __half* pb = &Bs[buf][(wn0 + nt * 8 + g) * LDSH + 2 * tig];
            b[nt][0] = *reinterpret_cast<const uint32_t*>(pb);
            b[nt][1] = *reinterpret_cast<const uint32_t*>(pb + 8);
        }
        #pragma unroll
        for (int mt = 0; mt < 4; mt++)
            #pragma unroll
            for (int nt = 0; nt < WNT; nt++)
                mma16(acc[mt][nt], a[mt], b[nt]);
    };

    // prologue: stages 0..S-2
    #pragma unroll
    for (int j = 0; j < S - 1; j++) load(j);

    const int NC = K / BK;                       // 16
    for (int c = 0; c < NC; c++) {
        CP_WAIT2();                              // chunk c's group complete
        __syncthreads();
        compute(c % S);
        int j = c + S - 1;
        if (j < NC) load(j);                     // into buf (c-1)%S: safe post-sync
    }

    // epilogue: fp16 output (N = Ntot = 64, single N-tile)
    #pragma unroll
    for (int mt = 0; mt < 4; mt++) {
        int r0 = blockM + wm0 + mt * 16 + g;
        int r1 = r0 + 8;
        #pragma unroll
        for (int nt = 0; nt < WNT; nt++) {
            int cb = wn0 + nt * 8 + 2 * tig;
            if (r0 < M)
                *reinterpret_cast<uint32_t*>(&C[(size_t)r0 * Ntot + cb]) =
                    f2h2(acc[mt][nt][0], acc[mt][nt][1]);
            if (r1 < M)
                *reinterpret_cast<uint32_t*>(&C[(size_t)r1 * Ntot + cb]) =
                    f2h2(acc[mt][nt][2], acc[mt][nt][3]);
        }
    }
}

// ===========================================================================
// Fused setup: weight transposes (fp32->fp16) + row_ptr, one launch.
// ===========================================================================
__global__ void setup_kernel(const float* __restrict__ w1, __half* __restrict__ w1t,
                             const float* __restrict__ w2, __half* __restrict__ w2t,
                             int sz1, int n1, int k1, int sz2, int n2, int k2,
                             const int* __restrict__ row, int* __restrict__ rp,
                             int E, int N)
{
    int i = blockIdx.x * blockDim.x + threadIdx.x;
    if (i < sz1) {
        int k = i / n1, n = i % n1;
        w1t[(size_t)n * k1 + k] = __float2half_rn(w1[i]);
    } else if (i < sz1 + sz2) {
        int j = i - sz1;
        int k = j / n2, n = j % n2;
        w2t[(size_t)n * k2 + k] = __float2half_rn(w2[j]);
    }
    if (i < E) {
        int r0 = row[i];
        int r1 = (i + 1 < E) ? row[i + 1] : N;
        for (int r = r0 + 1; r <= r1; r++) rp[r] = i + 1;
        if (i == 0)
            for (int r = 0; r <= r0; r++) rp[r] = 0;
    }
}

// ---------------------------------------------------------------------------
// CSR SpMM, fp16 src -> fp16 dst (layer 1, F=256).
// T=32 threads/row, uint4 (8-half) per thread; fp32 accumulate; direct store.
// ---------------------------------------------------------------------------
__global__ void __launch_bounds__(256)
spmm_csr_h2h(const __half* __restrict__ src, const float* __restrict__ bias,
             const float* __restrict__ ew, const int* __restrict__ rp,
             const int* __restrict__ col, __half* __restrict__ dst, int N)
{
    constexpr int T = 32;
    constexpr int G = 256 / T;
    const int g = threadIdx.x / T;
    const int f = threadIdx.x % T;
    const int r = blockIdx.x * G + g;
    if (r >= N) return;

    const int s = __ldg(&rp[r]);
    const int e_end = __ldg(&rp[r + 1]);

    float a[8];
    #pragma unroll
    for (int q = 0; q < 8; q++) a[q] = 0.f;
    const uint4* src4 = reinterpret_cast<const uint4*>(src) + f;

    int i = s;
    for (; i + 4 <= e_end; i += 4) {
        float w[4]; uint4 v[4];
        #pragma unroll
        for (int j = 0; j < 4; j++) {
            int c = __ldg(&col[i + j]);
            w[j]  = __ldg(&ew[i + j]);
            v[j]  = __ldg(&src4[(size_t)c * T]);
        }
        #pragma unroll
        for (int j = 0; j < 4; j++) acc8(a, v[j], w[j]);
    }
    for (; i < e_end; i++) {
        int c = __ldg(&col[i]);
        float w = __ldg(&ew[i]);
        uint4 v = __ldg(&src4[(size_t)c * T]);
        acc8(a, v, w);
    }

    const float4* bias4 = reinterpret_cast<const float4*>(bias);
    float4 b0 = __ldg(&bias4[2 * f]);
    float4 b1 = __ldg(&bias4[2 * f + 1]);
    uint4 o;
    o.x = f2h2(a[0] + b0.x, a[1] + b0.y);
    o.y = f2h2(a[2] + b0.z, a[3] + b0.w);
    o.z = f2h2(a[4] + b1.x, a[5] + b1.y);
    o.w = f2h2(a[6] + b1.z, a[7] + b1.w);
    *(reinterpret_cast<uint4*>(dst) + (size_t)r * T + f) = o;
}

// ---------------------------------------------------------------------------
// CSR SpMM, fp16 src -> fp32 dst (layer 2, F=64). T=8 x uint4.
// ---------------------------------------------------------------------------
__global__ void __launch_bounds__(256)
spmm_csr_h2f(const __half* __restrict__ src, const float* __restrict__ bias,
             const float* __restrict__ ew, const int* __restrict__ rp,
             const int* __restrict__ col, float* __restrict__ dst, int N)
{
    constexpr int T = 8;
    constexpr int G = 256 / T;
    const int g = threadIdx.x / T;
    const int f = threadIdx.x % T;
    const int r = blockIdx.x * G + g;
    if (r >= N) return;

    const int s = __ldg(&rp[r]);
    const int e_end = __ldg(&rp[r + 1]);

    float a[8];
    #pragma unroll
    for (int q = 0; q < 8; q++) a[q] = 0.f;
    const uint4* src4 = reinterpret_cast<const uint4*>(src) + f;

    int i = s;
    for (; i + 4 <= e_end; i += 4) {
        float w[4]; uint4 v[4];
        #pragma unroll
        for (int j = 0; j < 4; j++) {
            int c = __ldg(&col[i + j]);
            w[j]  = __ldg(&ew[i + j]);
            v[j]  = __ldg(&src4[(size_t)c * T]);
        }
        #pragma unroll
        for (int j = 0; j < 4; j++) acc8(a, v[j], w[j]);
    }
    for (; i < e_end; i++) {
        int c = __ldg(&col[i]);
        float w = __ldg(&ew[i]);
        uint4 v = __ldg(&src4[(size_t)c * T]);
        acc8(a, v, w);
    }

    const float4* bias4 = reinterpret_cast<const float4*>(bias);
    float4 b0 = __ldg(&bias4[2 * f]);
    float4 b1 = __ldg(&bias4[2 * f + 1]);
    float4* d = reinterpret_cast<float4*>(dst) + (size_t)r * (2 * T) + 2 * f;
    d[0] = make_float4(a[0] + b0.x, a[1] + b0.y, a[2] + b0.z, a[3] + b0.w);
    d[1] = make_float4(a[4] + b1.x, a[5] + b1.y, a[6] + b1.z, a[7] + b1.w);
}

// ===========================================================================
extern "C" void kernel_launch(void* const* d_in, const int* in_sizes, int n_in,
                              void* d_out, int out_size)
{
    const float* x   = (const float*)d_in[0];
    const float* w1  = (const float*)d_in[1];
    const float* b1  = (const float*)d_in[2];
    const float* w2  = (const float*)d_in[3];
    const float* b2  = (const float*)d_in[4];
    const float* ew  = (const float*)d_in[5];
    const int*   row = (const int*)d_in[6];
    const int*   col = (const int*)d_in[7];

    const int nhid  = in_sizes[2];            // 256
    const int nout  = in_sizes[4];            // 64
    const int nfeat = in_sizes[1] / nhid;     // 512
    const int n     = in_sizes[0] / nfeat;    // 50000
    const int E     = in_sizes[5];            // 800000

    void *p1, *p2, *p3, *p4, *p5, *p6;
    cudaGetSymbolAddress(&p1, g_h1);
    cudaGetSymbolAddress(&p2, g_h2);
    cudaGetSymbolAddress(&p3, g_h3);
    cudaGetSymbolAddress(&p4, g_w1t);
    cudaGetSymbolAddress(&p5, g_w2t);
    cudaGetSymbolAddress(&p6, g_rowptr);
    __half* h1  = (__half*)p1;
    __half* h2  = (__half*)p2;
    __half* h3  = (__half*)p3;
    __half* w1t = (__half*)p4;
    __half* w2t = (__half*)p5;
    int*    rp  = (int*)p6;
    float*  out = (float*)d_out;

    const int tilesM = (n + 127) / 128;                   // 391

    // 0) fused setup: W transposes + row_ptr (one launch)
    {
        int sz1 = nfeat * nhid, sz2 = nhid * nout;
        int total = (E > sz1 + sz2) ? E : (sz1 + sz2);
        setup_kernel<<<(total + 255) / 256, 256>>>(
            w1, w1t, w2, w2t, sz1, nhid, nfeat, sz2, nout, nhid,
            row, rp, E, n);
    }

    // 1) h1 = x @ W1   (R12-proven: BK=32, BN=128, fp16 out)
    {
        dim3 grid(nhid / 128, tilesM);
        gemm1_mma<<<grid, 128>>>(x, w1t, h1, n, nfeat, nhid);
    }

    // 2) h2 = b1 + A @ h1   (CSR, T=32 x uint4)
    spmm_csr_h2h<<<(n + 7) / 8, 256>>>(h1, b1, ew, rp, col, h2, n);

    // 3) h3 = relu(h2) @ W2   (4-stage cp.async pipeline; relu on fragments)
    gemm2_mma<<<tilesM, 256>>>(h2, w2t, h3, n, nhid, nout);

    // 4) out = b2 + A @ h3   (CSR, T=8 x uint4, fp32 out)
    spmm_csr_h2f<<<(n + 31) / 32, 256>>>(h3, b2, ew, rp, col, out, n);
}

// round 15
// speedup vs baseline: 1.2202x; 1.2202x over previous
#include <cuda_runtime.h>
#include <cuda_fp16.h>
#include <cstdint>

// Problem constants (fixed by dataset)
#define MAXN   50000
#define NFEAT  512
#define FHID   256
#define FOUT   64

// Scratch (device globals: allocation-free per harness rules)
__device__ __align__(16) __half g_h1 [MAXN * FHID];    // x @ W1          (fp16)
__device__ __align__(16) __half g_h2 [MAXN * FHID];    // spmm(h1) + b1   (fp16)
__device__ __align__(16) __half g_h3 [MAXN * FOUT];    // relu(h2) @ W2   (fp16)
__device__ __align__(16) __half g_w1t[FHID * NFEAT];   // W1^T fp16
__device__ __align__(16) __half g_w2t[FOUT * FHID];    // W2^T fp16
__device__ int g_rowptr[MAXN + 1];

// ===========================================================================
// helpers
// ===========================================================================
__device__ __forceinline__ uint32_t smem_u32(const void* p) {
    uint32_t a;
    asm("{ .reg .u64 t; cvta.to.shared.u64 t, %1; cvt.u32.u64 %0, t; }"
        : "=r"(a) : "l"(p));
    return a;
}
__device__ __forceinline__ void cp16(uint32_t dst, const void* src) {
    asm volatile("cp.async.cg.shared.global [%0], [%1], 16;"
                 :: "r"(dst), "l"(src) : "memory");
}
#define CP_COMMIT() asm volatile("cp.async.commit_group;" ::: "memory")
#define CP_WAIT0()  asm volatile("cp.async.wait_group 0;" ::: "memory")

// mma.sync m16n8k16 fp16 inputs, fp32 accum (base PTX, sm_80+)
__device__ __forceinline__ void mma16(float* d, const uint32_t* a, const uint32_t* b) {
    asm volatile(
        "mma.sync.aligned.m16n8k16.row.col.f32.f16.f16.f32 "
        "{%0,%1,%2,%3}, {%4,%5,%6,%7}, {%8,%9}, {%0,%1,%2,%3};"
        : "+f"(d[0]), "+f"(d[1]), "+f"(d[2]), "+f"(d[3])
        : "r"(a[0]), "r"(a[1]), "r"(a[2]), "r"(a[3]), "r"(b[0]), "r"(b[1]));
}

__device__ __forceinline__ uint32_t f2h2(float x, float y) {
    __half2 h = __floats2half2_rn(x, y);
    return *reinterpret_cast<uint32_t*>(&h);
}

// accumulate 8 halves (uint4) * w into fp32 acc[8]
__device__ __forceinline__ void acc8(float* a, uint4 v, float w) {
    const uint32_t* u = reinterpret_cast<const uint32_t*>(&v);
    #pragma unroll
    for (int q = 0; q < 4; q++) {
        float2 f = __half22float2(*reinterpret_cast<const __half2*>(&u[q]));
        a[2*q]   = fmaf(w, f.x, a[2*q]);
        a[2*q+1] = fmaf(w, f.y, a[2*q+1]);
    }
}

// ===========================================================================
// GEMM1 (R12-proven): 4 warps, warp tile 64x64, BM=128, BN=128, BK=32.
// A fp32 (cvt fp16 in registers), Bt fp16, C fp16.  LDSH=40 conflict-free.
// ===========================================================================
__global__ void __launch_bounds__(128)
gemm1_mma(const float* __restrict__ A, const __half* __restrict__ Bt,
          __half* __restrict__ C, int M, int K, int Ntot)
{
    constexpr int BM = 128, BN = 128, BK = 32, LDSH = 40;
    __shared__ __half As[2][BM * LDSH];
    __shared__ __half Bs[2][BN * LDSH];

    const int tid  = threadIdx.x;
    const int lane = tid & 31, wid = tid >> 5;
    const int g    = lane >> 2, tig = lane & 3;
    const int wm0  = (wid >> 1) * 64;
    const int wn0  = (wid & 1) * 64;
    const int blockM = blockIdx.y * BM;
    const int blockN = blockIdx.x * BN;

    const int arow = tid >> 3;                   // 0..15 (A rows: arow + 16i)
    const int aq   = tid & 7;

    float acc[4][8][4];
    #pragma unroll
    for (int mt = 0; mt < 4; mt++)
        #pragma unroll
        for (int nt = 0; nt < 8; nt++)
            #pragma unroll
            for (int i = 0; i < 4; i++) acc[mt][nt][i] = 0.f;

    auto ldgA = [&](int c, float4* av) {
        const int k0 = c * BK;
        #pragma unroll
        for (int i = 0; i < 8; i++) {
            int r = blockM + arow + i * 16;
            if (r < M)
                av[i] = *reinterpret_cast<const float4*>(&A[(size_t)r * K + k0 + aq * 4]);
            else
                av[i] = make_float4(0.f, 0.f, 0.f, 0.f);
        }
    };
    auto stsA = [&](int buf, float4* av) {
        #pragma unroll
        for (int i = 0; i < 8; i++) {
            float4 v = av[i];
            uint2 h = make_uint2(f2h2(v.x, v.y), f2h2(v.z, v.w));
            *reinterpret_cast<uint2*>(&As[buf][(arow + i * 16) * LDSH + aq * 4]) = h;
        }
    };
    auto cpB = [&](int c, int buf) {
        const int k0 = c * BK;
        #pragma unroll
        for (int i = 0; i < 4; i++) {
            int u = tid + i * 128;
            int r = u >> 2, q = u & 3;
            cp16(smem_u32(&Bs[buf][r * LDSH + q * 8]),
                 &Bt[(size_t)(blockN + r) * K + k0 + q * 8]);
        }
        CP_COMMIT();
    };
    auto compute = [&](int buf) {
        #pragma unroll
        for (int ks = 0; ks < 2; ks++) {
            uint32_t a[4][4], b[8][2];
            #pragma unroll
            for (int mt = 0; mt < 4; mt++) {
                const __half* p = &As[buf][(wm0 + mt * 16 + g) * LDSH + ks * 16 + 2 * tig];
                a[mt][0] = *reinterpret_cast<const uint32_t*>(p);
                a[mt][1] = *reinterpret_cast<const uint32_t*>(p + 8 * LDSH);
                a[mt][2] = *reinterpret_cast<const uint32_t*>(p + 8);
                a[mt][3] = *reinterpret_cast<const uint32_t*>(p + 8 * LDSH + 8);
            }
            #pragma unroll
            for (int nt = 0; nt < 8; nt++) {
                const __half* pb = &Bs[buf][(wn0 + nt * 8 + g) * LDSH + ks * 16 + 2 * tig];
                b[nt][0] = *reinterpret_cast<const uint32_t*>(pb);
                b[nt][1] = *reinterpret_cast<const uint32_t*>(pb + 8);
            }
            #pragma unroll
            for (int mt = 0; mt < 4; mt++)
                #pragma unroll
                for (int nt = 0; nt < 8; nt++)
                    mma16(acc[mt][nt], a[mt], b[nt]);
        }
    };

    {
        float4 av[8];
        ldgA(0, av);
        cpB(0, 0);
        stsA(0, av);
        CP_WAIT0();
        __syncthreads();
    }

    const int NC = K / BK;                       // 16
    for (int c = 0; c < NC; c++) {
        float4 av[8];
        const bool more = (c + 1 < NC);
        if (more) {
            ldgA(c + 1, av);
            cpB(c + 1, (c + 1) & 1);
        }
        compute(c & 1);
        if (more) {
            stsA((c + 1) & 1, av);
            CP_WAIT0();
            __syncthreads();
        }
    }

    #pragma unroll
    for (int mt = 0; mt < 4; mt++) {
        int r0 = blockM + wm0 + mt * 16 + g;
        int r1 = r0 + 8;
        #pragma unroll
        for (int nt = 0; nt < 8; nt++) {
            int cb = blockN + wn0 + nt * 8 + 2 * tig;
            if (r0 < M)
                *reinterpret_cast<uint32_t*>(&C[(size_t)r0 * Ntot + cb]) =
                    f2h2(acc[mt][nt][0], acc[mt][nt][1]);
            if (r1 < M)
                *reinterpret_cast<uint32_t*>(&C[(size_t)r1 * Ntot + cb]) =
                    f2h2(acc[mt][nt][2], acc[mt][nt][3]);
        }
    }
}

// ===========================================================================
// GEMM2 (R12-proven): 8 warps (2Mx4N), BM=128, BN=64, BK=16.
// A fp16 (h2) with relu in register staging; Bt fp16; C fp16.
// ===========================================================================
__global__ void __launch_bounds__(256)
gemm2_mma(const __half* __restrict__ A, const __half* __restrict__ Bt,
          __half* __restrict__ C, int M, int K, int Ntot)
{
    constexpr int BM = 128, BN = 64, BK = 16, LDSH = 24, WNT = 2;
    __shared__ __half As[2][BM * LDSH];
    __shared__ __half Bs[2][BN * LDSH];

    const int tid  = threadIdx.x;
    const int lane = tid & 31, wid = tid >> 5;
    const int g    = lane >> 2, tig = lane & 3;
    const int wm0  = (wid >> 2) * 64;
    const int wn0  = (wid & 3) * (BN / 4);
    const int blockM = blockIdx.y * BM;
    const int blockN = blockIdx.x * BN;

    const int arow = tid >> 1;                   // 0..127
    const int aq   = tid & 1;

    float acc[4][WNT][4];
    #pragma unroll
    for (int mt = 0; mt < 4; mt++)
        #pragma unroll
        for (int nt = 0; nt < WNT; nt++)
            #pragma unroll
            for (int i = 0; i < 4; i++) acc[mt][nt][i] = 0.f;

    const __half2 hzero = __floats2half2_rn(0.f, 0.f);

    auto ldgA = [&](int c, uint4* av) {
        const int k0 = c * BK;
        int r = blockM + arow;
        if (r < M)
            *av = *reinterpret_cast<const uint4*>(&A[(size_t)r * K + k0 + aq * 8]);
        else
            *av = make_uint4(0u, 0u, 0u, 0u);
    };
    auto stsA = [&](int buf, uint4 v) {
        __half2* h = reinterpret_cast<__half2*>(&v);
        #pragma unroll
        for (int i = 0; i < 4; i++) h[i] = __hmax2(h[i], hzero);   // relu
        *reinterpret_cast<uint4*>(&As[buf][arow * LDSH + aq * 8]) = v;
    };
    auto cpB = [&](int c, int buf) {
        const int k0 = c * BK;
        if (tid < BN * 2) {
            int r = tid >> 1, q = tid & 1;
            cp16(smem_u32(&Bs[buf][r * LDSH + q * 8]),
                 &Bt[(size_t)(blockN + r) * K + k0 + q * 8]);
        }
        CP_COMMIT();
    };
    auto compute = [&](int buf) {
        uint32_t a[4][4], b[WNT][2];
        #pragma unroll
        for (int mt = 0; mt < 4; mt++) {
            const __half* p = &As[buf][(wm0 + mt * 16 + g) * LDSH + 2 * tig];
            a[mt][0] = *reinterpret_cast<const uint32_t*>(p);
            a[mt][1] = *reinterpret_cast<const uint32_t*>(p + 8 * LDSH);
            a[mt][2] = *reinterpret_cast<const uint32_t*>(p + 8);
            a[mt][3] = *reinterpret_cast<const uint32_t*>(p + 8 * LDSH + 8);
        }
        #pragma unroll
        for (int nt = 0; nt < WNT; nt++) {
            const __half* pb = &Bs[buf][(wn0 + nt * 8 + g) * LDSH + 2 * tig];
            b[nt][0] = *reinterpret_cast<const uint32_t*>(pb);
            b[nt][1] = *reinterpret_cast<const uint32_t*>(pb + 8);
        }
        #pragma unroll
        for (int mt = 0; mt < 4; mt++)
            #pragma unroll
            for (int nt = 0; nt < WNT; nt++)
                mma16(acc[mt][nt], a[mt], b[nt]);
    };

    {
        uint4 av;
        ldgA(0, &av);
        cpB(0, 0);
        stsA(0, av);
        CP_WAIT0();
        __syncthreads();
    }

    const int NC = K / BK;
    for (int c = 0; c < NC; c++) {
        uint4 av;
        const bool more = (c + 1 < NC);
        if (more) {
            ldgA(c + 1, &av);
            cpB(c + 1, (c + 1) & 1);
        }
        compute(c & 1);
        if (more) {
            stsA((c + 1) & 1, av);
            CP_WAIT0();
            __syncthreads();
        }
    }

    #pragma unroll
    for (int mt = 0; mt < 4; mt++) {
        int r0 = blockM + wm0 + mt * 16 + g;
        int r1 = r0 + 8;
        #pragma unroll
        for (int nt = 0; nt < WNT; nt++) {
            int cb = blockN + wn0 + nt * 8 + 2 * tig;
            if (r0 < M)
                *reinterpret_cast<uint32_t*>(&C[(size_t)r0 * Ntot + cb]) =
                    f2h2(acc[mt][nt][0], acc[mt][nt][1]);
            if (r1 < M)
                *reinterpret_cast<uint32_t*>(&C[(size_t)r1 * Ntot + cb]) =
                    f2h2(acc[mt][nt][2], acc[mt][nt][3]);
        }
    }
}

// ===========================================================================
// Fused setup: weight transposes (fp32->fp16) + row_ptr, one launch.
// ===========================================================================
__global__ void setup_kernel(const float* __restrict__ w1, __half* __restrict__ w1t,
                             const float* __restrict__ w2, __half* __restrict__ w2t,
                             int sz1, int n1, int k1, int sz2, int n2, int k2,
                             const int* __restrict__ row, int* __restrict__ rp,
                             int E, int N)
{
    int i = blockIdx.x * blockDim.x + threadIdx.x;
    if (i < sz1) {
        int k = i / n1, n = i % n1;
        w1t[(size_t)n * k1 + k] = __float2half_rn(w1[i]);
    } else if (i < sz1 + sz2) {
        int j = i - sz1;
        int k = j / n2, n = j % n2;
        w2t[(size_t)n * k2 + k] = __float2half_rn(w2[j]);
    }
    if (i < E) {
        int r0 = row[i];
        int r1 = (i + 1 < E) ? row[i + 1] : N;
        for (int r = r0 + 1; r <= r1; r++) rp[r] = i + 1;
        if (i == 0)
            for (int r = 0; r <= r0; r++) rp[r] = 0;
    }
}

// ---------------------------------------------------------------------------
// CSR SpMM, fp16 src -> fp16 dst (layer 1, F=256).
// T=32 threads/row, uint4 (8-half) per thread; fp32 accumulate; direct store.
// ---------------------------------------------------------------------------
__global__ void __launch_bounds__(256)
spmm_csr_h2h(const __half* __restrict__ src, const float* __restrict__ bias,
             const float* __restrict__ ew, const int* __restrict__ rp,
             const int* __restrict__ col, __half* __restrict__ dst, int N)
{
    constexpr int T = 32;
    constexpr int G = 256 / T;
    const int g = threadIdx.x / T;
    const int f = threadIdx.x % T;
    const int r = blockIdx.x * G + g;
    if (r >= N) return;

    const int s = __ldg(&rp[r]);
    const int e_end = __ldg(&rp[r + 1]);

    float a[8];
    #pragma unroll
    for (int q = 0; q < 8; q++) a[q] = 0.f;
    const uint4* src4 = reinterpret_cast<const uint4*>(src) + f;

    int i = s;
    for (; i + 4 <= e_end; i += 4) {
        float w[4]; uint4 v[4];
        #pragma unroll
        for (int j = 0; j < 4; j++) {
            int c = __ldg(&col[i + j]);
            w[j]  = __ldg(&ew[i + j]);
            v[j]  = __ldg(&src4[(size_t)c * T]);
        }
        #pragma unroll
        for (int j = 0; j < 4; j++) acc8(a, v[j], w[j]);
    }
    for (; i < e_end; i++) {
        int c = __ldg(&col[i]);
        float w = __ldg(&ew[i]);
        uint4 v = __ldg(&src4[(size_t)c * T]);
        acc8(a, v, w);
    }

    const float4* bias4 = reinterpret_cast<const float4*>(bias);
    float4 b0 = __ldg(&bias4[2 * f]);
    float4 b1 = __ldg(&bias4[2 * f + 1]);
    uint4 o;
    o.x = f2h2(a[0] + b0.x, a[1] + b0.y);
    o.y = f2h2(a[2] + b0.z, a[3] + b0.w);
    o.z = f2h2(a[4] + b1.x, a[5] + b1.y);
    o.w = f2h2(a[6] + b1.z, a[7] + b1.w);
    *(reinterpret_cast<uint4*>(dst) + (size_t)r * T + f) = o;
}

// ---------------------------------------------------------------------------
// CSR SpMM, fp16 src -> fp32 dst (layer 2, F=64). T=8 x uint4.
// ---------------------------------------------------------------------------
__global__ void __launch_bounds__(256)
spmm_csr_h2f(const __half* __restrict__ src, const float* __restrict__ bias,
             const float* __restrict__ ew, const int* __restrict__ rp,
             const int* __restrict__ col, float* __restrict__ dst, int N)
{
    constexpr int T = 8;
    constexpr int G = 256 / T;
    const int g = threadIdx.x / T;
    const int f = threadIdx.x % T;
    const int r = blockIdx.x * G + g;
    if (r >= N) return;

    const int s = __ldg(&rp[r]);
    const int e_end = __ldg(&rp[r + 1]);

    float a[8];
    #pragma unroll
    for (int q = 0; q < 8; q++) a[q] = 0.f;
    const uint4* src4 = reinterpret_cast<const uint4*>(src) + f;

    int i = s;
    for (; i + 4 <= e_end; i += 4) {
        float w[4]; uint4 v[4];
        #pragma unroll
        for (int j = 0; j < 4; j++) {
            int c = __ldg(&col[i + j]);
            w[j]  = __ldg(&ew[i + j]);
            v[j]  = __ldg(&src4[(size_t)c * T]);
        }
        #pragma unroll
        for (int j = 0; j < 4; j++) acc8(a, v[j], w[j]);
    }
    for (; i < e_end; i++) {
        int c = __ldg(&col[i]);
        float w = __ldg(&ew[i]);
        uint4 v = __ldg(&src4[(size_t)c * T]);
        acc8(a, v, w);
    }

    const float4* bias4 = reinterpret_cast<const float4*>(bias);
    float4 b0 = __ldg(&bias4[2 * f]);
    float4 b1 = __ldg(&bias4[2 * f + 1]);
    float4* d = reinterpret_cast<float4*>(dst) + (size_t)r * (2 * T) + 2 * f;
    d[0] = make_float4(a[0] + b0.x, a[1] + b0.y, a[2] + b0.z, a[3] + b0.w);
    d[1] = make_float4(a[4] + b1.x, a[5] + b1.y, a[6] + b1.z, a[7] + b1.w);
}

// ===========================================================================
extern "C" void kernel_launch(void* const* d_in, const int* in_sizes, int n_in,
                              void* d_out, int out_size)
{
    const float* x   = (const float*)d_in[0];
    const float* w1  = (const float*)d_in[1];
    const float* b1  = (const float*)d_in[2];
    const float* w2  = (const float*)d_in[3];
    const float* b2  = (const float*)d_in[4];
    const float* ew  = (const float*)d_in[5];
    const int*   row = (const int*)d_in[6];
    const int*   col = (const int*)d_in[7];

    const int nhid  = in_sizes[2];            // 256
    const int nout  = in_sizes[4];            // 64
    const int nfeat = in_sizes[1] / nhid;     // 512
    const int n     = in_sizes[0] / nfeat;    // 50000
    const int E     = in_sizes[5];            // 800000

    void *p1, *p2, *p3, *p4, *p5, *p6;
    cudaGetSymbolAddress(&p1, g_h1);
    cudaGetSymbolAddress(&p2, g_h2);
    cudaGetSymbolAddress(&p3, g_h3);
    cudaGetSymbolAddress(&p4, g_w1t);
    cudaGetSymbolAddress(&p5, g_w2t);
    cudaGetSymbolAddress(&p6, g_rowptr);
    __half* h1  = (__half*)p1;
    __half* h2  = (__half*)p2;
    __half* h3  = (__half*)p3;
    __half* w1t = (__half*)p4;
    __half* w2t = (__half*)p5;
    int*    rp  = (int*)p6;
    float*  out = (float*)d_out;

    const int tilesM = (n + 127) / 128;                   // 391

    // 0) fused setup: W transposes + row_ptr (one launch)
    {
        int sz1 = nfeat * nhid, sz2 = nhid * nout;
        int total = (E > sz1 + sz2) ? E : (sz1 + sz2);
        setup_kernel<<<(total + 255) / 256, 256>>>(
            w1, w1t, w2, w2t, sz1, nhid, nfeat, sz2, nout, nhid,
            row, rp, E, n);
    }

    // 1) h1 = x @ W1   (R12-proven: BK=32, BN=128, fp16 out)
    {
        dim3 grid(nhid / 128, tilesM);
        gemm1_mma<<<grid, 128>>>(x, w1t, h1, n, nfeat, nhid);
    }

    // 2) h2 = b1 + A @ h1   (CSR, T=32 x uint4)
    spmm_csr_h2h<<<(n + 7) / 8, 256>>>(h1, b1, ew, rp, col, h2, n);

    // 3) h3 = relu(h2) @ W2   (R12-proven: register-staged relu)
    {
        dim3 grid(nout / 64, tilesM);
        gemm2_mma<<<grid, 256>>>(h2, w2t, h3, n, nhid, nout);
    }

    // 4) out = b2 + A @ h3   (CSR, T=8 x uint4, fp32 out)
    spmm_csr_h2f<<<(n + 31) / 32, 256>>>(h3, b2, ew, rp, col, out, n);
}